// round 1
// baseline (speedup 1.0000x reference)
#include <cuda_runtime.h>

#define S_DIM 128
#define N_DIM 256
#define CM 256
#define CH 32
#define CZ 128
#define P_DIM (N_DIM * CH)   // 8192

#define LN_EPS 1e-5f
#define OPM_EPS 1e-3f

// ---- scratch (static __device__, allocation-free) ----
__device__ float g_a[P_DIM * S_DIM];               // a_t[p][s], p = n*32+h   (4 MB)
__device__ float g_b[P_DIM * S_DIM];               // b_t[q][s]               (4 MB)
__device__ float g_O[(size_t)P_DIM * P_DIM];       // outer accumulator       (256 MB)
__device__ float g_norm[N_DIM * N_DIM];            // mask^T mask + eps

// ============================================================================
// Kernel 1: LayerNorm + dual projection + mask.  One block per (s, n) row.
// ============================================================================
__global__ void ln_proj_kernel(const float* __restrict__ m,
                               const float* __restrict__ mask,
                               const float* __restrict__ ln_w,
                               const float* __restrict__ ln_b,
                               const float* __restrict__ w1,
                               const float* __restrict__ b1,
                               const float* __restrict__ w2,
                               const float* __restrict__ b2) {
    const int row = blockIdx.x;            // s*N + n
    const int s = row >> 8;                // row / 256
    const int n = row & 255;
    const int tid = threadIdx.x;           // 256 threads, one per c_m element

    __shared__ float sh_ln[CM];
    __shared__ float wsum[8], wsum2[8];
    __shared__ float s_mu, s_rstd;
    __shared__ float part[4][64];

    float x = m[(size_t)row * CM + tid];

    // block reduction for mean / var
    float v = x, v2 = x * x;
    #pragma unroll
    for (int o = 16; o > 0; o >>= 1) {
        v  += __shfl_xor_sync(0xffffffff, v,  o);
        v2 += __shfl_xor_sync(0xffffffff, v2, o);
    }
    const int warp = tid >> 5, lane = tid & 31;
    if (lane == 0) { wsum[warp] = v; wsum2[warp] = v2; }
    __syncthreads();
    if (tid == 0) {
        float t = 0.f, t2 = 0.f;
        #pragma unroll
        for (int i = 0; i < 8; i++) { t += wsum[i]; t2 += wsum2[i]; }
        float mu  = t * (1.0f / CM);
        float var = t2 * (1.0f / CM) - mu * mu;
        s_mu = mu;
        s_rstd = rsqrtf(var + LN_EPS);
    }
    __syncthreads();

    sh_ln[tid] = (x - s_mu) * s_rstd * ln_w[tid] + ln_b[tid];
    __syncthreads();

    // 64 outputs (32 for a, 32 for b); 4 partial-sum groups over c_m quarters
    const int g = tid >> 6;        // 0..3  (k-quarter)
    const int o = tid & 63;        // output id
    const int h = o & 31;
    const float* __restrict__ w = (o < 32) ? w1 : w2;
    float acc = 0.f;
    const int k0 = g * 64;
    #pragma unroll 16
    for (int k = k0; k < k0 + 64; k++)
        acc += sh_ln[k] * w[k * CH + h];
    part[g][o] = acc;
    __syncthreads();

    if (tid < 64) {
        float mk = mask[s * N_DIM + n];
        float sum = part[0][tid] + part[1][tid] + part[2][tid] + part[3][tid];
        if (tid < 32) {
            g_a[(size_t)(n * CH + tid) * S_DIM + s] = (sum + b1[tid]) * mk;
        } else {
            g_b[(size_t)(n * CH + h) * S_DIM + s] = (sum + b2[h]) * mk;
        }
    }
}

// ============================================================================
// Kernel 2: norm[i][j] = sum_s mask[s][i]*mask[s][j] + eps
// ============================================================================
__global__ void norm_kernel(const float* __restrict__ mask) {
    const int i = blockIdx.x;
    const int j = threadIdx.x;     // 256
    __shared__ float mi[S_DIM];
    if (j < S_DIM) mi[j] = mask[j * N_DIM + i];
    __syncthreads();
    float acc = 0.f;
    #pragma unroll 8
    for (int s = 0; s < S_DIM; s++)
        acc += mi[s] * mask[s * N_DIM + j];
    g_norm[i * N_DIM + j] = acc + OPM_EPS;
}

// ============================================================================
// Kernel 3: O[8192,8192] = A[8192,128] * B[8192,128]^T   (both K-contiguous)
// 128x128 block tile, 8x8 microtile, BK=16, double-buffered smem.
// ============================================================================
__global__ void __launch_bounds__(256, 2) gemm1_kernel() {
    const int p0 = blockIdx.y * 128;
    const int q0 = blockIdx.x * 128;

    __shared__ float As[2][16][132];
    __shared__ float Bs[2][16][132];

    const int tid = threadIdx.x;
    const int tx = tid & 15, ty = tid >> 4;
    const int lp = tid >> 2;              // 0..63 (row within tile; +64 second pass)
    const int lk = (tid & 3) * 4;         // 0,4,8,12 (k offset within chunk)

    float acc[8][8];
    #pragma unroll
    for (int i = 0; i < 8; i++)
        #pragma unroll
        for (int j = 0; j < 8; j++) acc[i][j] = 0.f;

    float4 ra[2], rb[2];

    // prologue: chunk 0
    #pragma unroll
    for (int it = 0; it < 2; it++) {
        int p = lp + it * 64;
        ra[it] = *(const float4*)&g_a[(size_t)(p0 + p) * S_DIM + lk];
        rb[it] = *(const float4*)&g_b[(size_t)(q0 + p) * S_DIM + lk];
    }
    #pragma unroll
    for (int it = 0; it < 2; it++) {
        int p = lp + it * 64;
        As[0][lk + 0][p] = ra[it].x; As[0][lk + 1][p] = ra[it].y;
        As[0][lk + 2][p] = ra[it].z; As[0][lk + 3][p] = ra[it].w;
        Bs[0][lk + 0][p] = rb[it].x; Bs[0][lk + 1][p] = rb[it].y;
        Bs[0][lk + 2][p] = rb[it].z; Bs[0][lk + 3][p] = rb[it].w;
    }
    __syncthreads();

    int buf = 0;
    for (int kc = 0; kc < S_DIM; kc += 16) {
        const int next = kc + 16;
        if (next < S_DIM) {
            #pragma unroll
            for (int it = 0; it < 2; it++) {
                int p = lp + it * 64;
                ra[it] = *(const float4*)&g_a[(size_t)(p0 + p) * S_DIM + next + lk];
                rb[it] = *(const float4*)&g_b[(size_t)(q0 + p) * S_DIM + next + lk];
            }
        }
        #pragma unroll
        for (int kk = 0; kk < 16; kk++) {
            float4 a0 = *(const float4*)&As[buf][kk][ty * 4];
            float4 a1 = *(const float4*)&As[buf][kk][ty * 4 + 64];
            float4 b0 = *(const float4*)&Bs[buf][kk][tx * 4];
            float4 b1 = *(const float4*)&Bs[buf][kk][tx * 4 + 64];
            float ar[8] = {a0.x, a0.y, a0.z, a0.w, a1.x, a1.y, a1.z, a1.w};
            float br[8] = {b0.x, b0.y, b0.z, b0.w, b1.x, b1.y, b1.z, b1.w};
            #pragma unroll
            for (int i = 0; i < 8; i++)
                #pragma unroll
                for (int j = 0; j < 8; j++)
                    acc[i][j] += ar[i] * br[j];
        }
        if (next < S_DIM) {
            const int nb = buf ^ 1;
            #pragma unroll
            for (int it = 0; it < 2; it++) {
                int p = lp + it * 64;
                As[nb][lk + 0][p] = ra[it].x; As[nb][lk + 1][p] = ra[it].y;
                As[nb][lk + 2][p] = ra[it].z; As[nb][lk + 3][p] = ra[it].w;
                Bs[nb][lk + 0][p] = rb[it].x; Bs[nb][lk + 1][p] = rb[it].y;
                Bs[nb][lk + 2][p] = rb[it].z; Bs[nb][lk + 3][p] = rb[it].w;
            }
            __syncthreads();
            buf = nb;
        }
    }

    #pragma unroll
    for (int rg = 0; rg < 2; rg++)
        #pragma unroll
        for (int e = 0; e < 4; e++) {
            const int r = rg * 64 + ty * 4 + e;
            const int ri = rg * 4 + e;
            const size_t base = (size_t)(p0 + r) * P_DIM + q0;
            float4 o0 = make_float4(acc[ri][0], acc[ri][1], acc[ri][2], acc[ri][3]);
            float4 o1 = make_float4(acc[ri][4], acc[ri][5], acc[ri][6], acc[ri][7]);
            *(float4*)&g_O[base + tx * 4]      = o0;
            *(float4*)&g_O[base + tx * 4 + 64] = o1;
        }
}

// ============================================================================
// Kernel 4: out[65536,128] = O'[65536,1024] @ wo[1024,128]  (+bo, /norm)
// O'[m][k] = g_O[(i*32 + k/32)*8192 + (m%256)*32 + k%32],  m = i*256 + j
// ============================================================================
__global__ void __launch_bounds__(256, 2) gemm2_kernel(const float* __restrict__ wo,
                                                       const float* __restrict__ bo,
                                                       float* __restrict__ out) {
    const int m0 = blockIdx.x * 128;
    const int i_idx = m0 >> 8;          // fixed i for this block (128 | 256)
    const int j0 = m0 & 255;            // 0 or 128

    __shared__ float As[2][16][132];
    __shared__ float Bs[2][16][132];

    const int tid = threadIdx.x;
    const int tx = tid & 15, ty = tid >> 4;
    const int lr = tid >> 2;              // 0..63
    const int lk = (tid & 3) * 4;         // 0,4,8,12
    const int lbk = tid >> 5;             // 0..7  (+8 second pass)
    const int lbz = (tid & 31) * 4;       // 0..124

    float acc[8][8];
    #pragma unroll
    for (int i = 0; i < 8; i++)
        #pragma unroll
        for (int j = 0; j < 8; j++) acc[i][j] = 0.f;

    float4 ra[2], rb[2];

    // prologue: chunk kc = 0  (c = 0, d0 = 0)
    {
        const size_t rowbase = (size_t)(i_idx * 32) * P_DIM;
        #pragma unroll
        for (int it = 0; it < 2; it++) {
            int r = lr + it * 64;
            ra[it] = *(const float4*)&g_O[rowbase + (size_t)(j0 + r) * 32 + lk];
            rb[it] = *(const float4*)&wo[(lbk + it * 8) * CZ + lbz];
        }
        #pragma unroll
        for (int it = 0; it < 2; it++) {
            int r = lr + it * 64;
            As[0][lk + 0][r] = ra[it].x; As[0][lk + 1][r] = ra[it].y;
            As[0][lk + 2][r] = ra[it].z; As[0][lk + 3][r] = ra[it].w;
            *(float4*)&Bs[0][lbk + it * 8][lbz] = rb[it];
        }
    }
    __syncthreads();

    int buf = 0;
    #pragma unroll 1
    for (int kc = 0; kc < CH * CH; kc += 16) {
        const int next = kc + 16;
        if (next < CH * CH) {
            const size_t rowbase = (size_t)(i_idx * 32 + (next >> 5)) * P_DIM;
            const int d0 = next & 31;
            #pragma unroll
            for (int it = 0; it < 2; it++) {
                int r = lr + it * 64;
                ra[it] = *(const float4*)&g_O[rowbase + (size_t)(j0 + r) * 32 + d0 + lk];
                rb[it] = *(const float4*)&wo[(next + lbk + it * 8) * CZ + lbz];
            }
        }
        #pragma unroll
        for (int kk = 0; kk < 16; kk++) {
            float4 a0 = *(const float4*)&As[buf][kk][ty * 4];
            float4 a1 = *(const float4*)&As[buf][kk][ty * 4 + 64];
            float4 b0 = *(const float4*)&Bs[buf][kk][tx * 4];
            float4 b1 = *(const float4*)&Bs[buf][kk][tx * 4 + 64];
            float ar[8] = {a0.x, a0.y, a0.z, a0.w, a1.x, a1.y, a1.z, a1.w};
            float br[8] = {b0.x, b0.y, b0.z, b0.w, b1.x, b1.y, b1.z, b1.w};
            #pragma unroll
            for (int i = 0; i < 8; i++)
                #pragma unroll
                for (int j = 0; j < 8; j++)
                    acc[i][j] += ar[i] * br[j];
        }
        if (next < CH * CH) {
            const int nb = buf ^ 1;
            #pragma unroll
            for (int it = 0; it < 2; it++) {
                int r = lr + it * 64;
                As[nb][lk + 0][r] = ra[it].x; As[nb][lk + 1][r] = ra[it].y;
                As[nb][lk + 2][r] = ra[it].z; As[nb][lk + 3][r] = ra[it].w;
                *(float4*)&Bs[nb][lbk + it * 8][lbz] = rb[it];
            }
            __syncthreads();
            buf = nb;
        }
    }

    // epilogue: + bo, / norm
    const int c0 = tx * 4;
    float bo0[4], bo1[4];
    #pragma unroll
    for (int e = 0; e < 4; e++) { bo0[e] = bo[c0 + e]; bo1[e] = bo[c0 + 64 + e]; }

    #pragma unroll
    for (int rg = 0; rg < 2; rg++)
        #pragma unroll
        for (int e = 0; e < 4; e++) {
            const int r = rg * 64 + ty * 4 + e;
            const int ri = rg * 4 + e;
            const int mrow = m0 + r;
            const float inv = 1.0f / g_norm[mrow];
            const size_t base = (size_t)mrow * CZ;
            float4 o0, o1;
            o0.x = (acc[ri][0] + bo0[0]) * inv;
            o0.y = (acc[ri][1] + bo0[1]) * inv;
            o0.z = (acc[ri][2] + bo0[2]) * inv;
            o0.w = (acc[ri][3] + bo0[3]) * inv;
            o1.x = (acc[ri][4] + bo1[0]) * inv;
            o1.y = (acc[ri][5] + bo1[1]) * inv;
            o1.z = (acc[ri][6] + bo1[2]) * inv;
            o1.w = (acc[ri][7] + bo1[3]) * inv;
            *(float4*)&out[base + c0]      = o0;
            *(float4*)&out[base + c0 + 64] = o1;
        }
}

// ============================================================================
extern "C" void kernel_launch(void* const* d_in, const int* in_sizes, int n_in,
                              void* d_out, int out_size) {
    const float* m    = (const float*)d_in[0];
    const float* mask = (const float*)d_in[1];
    const float* ln_w = (const float*)d_in[2];
    const float* ln_b = (const float*)d_in[3];
    const float* w1   = (const float*)d_in[4];
    const float* b1   = (const float*)d_in[5];
    const float* w2   = (const float*)d_in[6];
    const float* b2   = (const float*)d_in[7];
    const float* wo   = (const float*)d_in[8];
    const float* bo   = (const float*)d_in[9];
    float* out = (float*)d_out;

    ln_proj_kernel<<<S_DIM * N_DIM, 256>>>(m, mask, ln_w, ln_b, w1, b1, w2, b2);
    norm_kernel<<<N_DIM, 256>>>(mask);

    dim3 g1(P_DIM / 128, P_DIM / 128);   // 64 x 64
    gemm1_kernel<<<g1, 256>>>();

    gemm2_kernel<<<(N_DIM * N_DIM) / 128, 256>>>(wo, bo, out);
}